// round 11
// baseline (speedup 1.0000x reference)
#include <cuda_runtime.h>
#include <cuda_bf16.h>
#include <cstdint>
#include <math.h>

#define BB   8
#define HD   128
#define WD   128
#define CC   256
#define HW   16384
#define NPLANE 2048
#define TWOPI 6.28318530717958647692f

// ---------------- scratch ----------------
__device__ float2 g_AF[CC * HW];
__device__ float2 g_BF[CC * HW];
__device__ float2 g_XF[NPLANE * HW];
__device__ float2 g_GA[NPLANE * HW];
__device__ float2 g_GB[NPLANE * HW];
__device__ __align__(16) __nv_bfloat16 g_WbHi[1024 * 256];   // [n][k], n = d*4+m
__device__ __align__(16) __nv_bfloat16 g_WbLo[1024 * 256];
__device__ __align__(16) __nv_bfloat16 g_XHi[131072 * 256];  // [pix][c] bf16 hi
__device__ __align__(16) __nv_bfloat16 g_XLo[131072 * 256];  // [pix][c] bf16 lo
__device__ float  g_bpk[1024];

// ---------------- complex helpers ----------------
__device__ __forceinline__ float2 cmul(float2 a, float2 b) {
    return make_float2(a.x * b.x - a.y * b.y, a.x * b.y + a.y * b.x);
}
__device__ __forceinline__ float2 cadd(float2 a, float2 b) { return make_float2(a.x + b.x, a.y + b.y); }
__device__ __forceinline__ float2 csub(float2 a, float2 b) { return make_float2(a.x - b.x, a.y - b.y); }
__device__ __forceinline__ float2 cconj(float2 a) { return make_float2(a.x, -a.y); }

__device__ __forceinline__ float2 shfl_xor_c(float2 v, int m) {
    float2 r;
    r.x = __shfl_xor_sync(0xffffffffu, v.x, m);
    r.y = __shfl_xor_sync(0xffffffffu, v.y, m);
    return r;
}

__device__ __forceinline__ uint32_t smem_u32(const void* p) {
    uint32_t a;
    asm("{ .reg .u64 t; cvta.to.shared.u64 t, %1; cvt.u32.u64 %0, t; }" : "=r"(a) : "l"(p));
    return a;
}
__device__ __forceinline__ void ldsm4(uint32_t* r, uint32_t addr) {
    asm volatile("ldmatrix.sync.aligned.m8n8.x4.shared.b16 {%0,%1,%2,%3}, [%4];"
                 : "=r"(r[0]), "=r"(r[1]), "=r"(r[2]), "=r"(r[3]) : "r"(addr));
}
__device__ __forceinline__ void mma16816(float* c, const uint32_t* a, const uint32_t* b) {
    asm volatile("mma.sync.aligned.m16n8k16.row.col.f32.bf16.bf16.f32 "
                 "{%0,%1,%2,%3}, {%4,%5,%6,%7}, {%8,%9}, {%0,%1,%2,%3};"
                 : "+f"(c[0]), "+f"(c[1]), "+f"(c[2]), "+f"(c[3])
                 : "r"(a[0]), "r"(a[1]), "r"(a[2]), "r"(a[3]), "r"(b[0]), "r"(b[1]));
}
__device__ __forceinline__ void cp16(uint32_t dst, const void* src) {
    asm volatile("cp.async.ca.shared.global [%0], [%1], 16;" :: "r"(dst), "l"(src) : "memory");
}
#define CP_COMMIT() asm volatile("cp.async.commit_group;" ::: "memory")
#define CP_WAIT1()  asm volatile("cp.async.wait_group 1;" ::: "memory")
#define CP_WAIT0()  asm volatile("cp.async.wait_group 0;" ::: "memory")

// 128-pt FFT: 4 regs x 32 lanes. Natural in; out reg k1 @ lane t = index 4*brev5(t)+k1.
template <int SGN>
__device__ __forceinline__ void fft128(float2 v[4], int lane) {
    float2 t0 = cadd(v[0], v[2]);
    float2 t1 = csub(v[0], v[2]);
    float2 t2 = cadd(v[1], v[3]);
    float2 t3 = csub(v[1], v[3]);
    float2 jt3 = make_float2(-t3.y, t3.x);
    float2 y0 = cadd(t0, t2);
    float2 y2 = csub(t0, t2);
    float2 y1, y3;
    if (SGN < 0) { y1 = csub(t1, jt3); y3 = cadd(t1, jt3); }
    else         { y1 = cadd(t1, jt3); y3 = csub(t1, jt3); }
    float ss, cc;
    __sincosf((float)SGN * TWOPI * (float)lane * (1.0f / 128.0f), &ss, &cc);
    float2 w1 = make_float2(cc, ss);
    float2 w2 = cmul(w1, w1);
    float2 w3 = cmul(w2, w1);
    v[0] = y0;
    v[1] = cmul(y1, w1);
    v[2] = cmul(y2, w2);
    v[3] = cmul(y3, w3);
#pragma unroll
    for (int h = 16; h >= 1; h >>= 1) {
        int j = lane & (h - 1);
        float ang = (float)SGN * TWOPI * (float)j / (float)(2 * h);
        float ws, wc;
        __sincosf(ang, &ws, &wc);
        float2 w = make_float2(wc, ws);
        bool hi = (lane & h) != 0;
#pragma unroll
        for (int k = 0; k < 4; k++) {
            float2 o = shfl_xor_c(v[k], h);
            if (hi) v[k] = cmul(csub(o, v[k]), w);
            else    v[k] = cadd(v[k], o);
        }
    }
}

// ---------------- K0: pack weights (bf16 hi/lo, [n][k]) + biases ----------------
__global__ void pack_kernel(const float* __restrict__ Wma, const float* __restrict__ Wpa,
                            const float* __restrict__ Wmb, const float* __restrict__ Wpb,
                            const float* __restrict__ bma, const float* __restrict__ bpa,
                            const float* __restrict__ bmb, const float* __restrict__ bpb) {
    int i = blockIdx.x * 256 + threadIdx.x;
    if (i < 1024 * 256) {
        int n = i >> 8, k = i & 255;
        int d = n >> 2, m = n & 3;
        const float* Wm = (m == 0) ? Wma : (m == 1) ? Wpa : (m == 2) ? Wmb : Wpb;
        float w = Wm[k * 256 + d];
        __nv_bfloat16 hi = __float2bfloat16(w);
        __nv_bfloat16 lo = __float2bfloat16(w - __bfloat162float(hi));
        g_WbHi[(size_t)n * 256 + k] = hi;
        g_WbLo[(size_t)n * 256 + k] = lo;
    }
    if (i < 1024) {
        int d = i >> 2, m = i & 3;
        const float* bv = (m == 0) ? bma : (m == 1) ? bpa : (m == 2) ? bmb : bpb;
        g_bpk[i] = bv[d];
    }
}

// ---------------- K1: freq-domain conv kernels (49-tap DFT) ----------------
__global__ void kfreq_kernel(const float* __restrict__ Ak, const float* __restrict__ Bk) {
    int w = threadIdx.x;
    int h = blockIdx.x;
    int c = blockIdx.y;
    __shared__ float ka[49], kb[49];
    if (threadIdx.x < 49) {
        ka[threadIdx.x] = Ak[c * 49 + threadIdx.x];
        kb[threadIdx.x] = Bk[c * 49 + threadIdx.x];
    }
    __syncthreads();
    float2 eh[7], ew[7];
    {
        float s, ct;
        sincosf(-TWOPI * (float)h * (1.0f / 128.0f), &s, &ct);
        float2 b1 = make_float2(ct, s);
        eh[3] = make_float2(1.f, 0.f);
        eh[4] = b1; eh[5] = cmul(b1, b1); eh[6] = cmul(eh[5], b1);
        eh[2] = cconj(eh[4]); eh[1] = cconj(eh[5]); eh[0] = cconj(eh[6]);
        sincosf(-TWOPI * (float)w * (1.0f / 128.0f), &s, &ct);
        float2 b2 = make_float2(ct, s);
        ew[3] = make_float2(1.f, 0.f);
        ew[4] = b2; ew[5] = cmul(b2, b2); ew[6] = cmul(ew[5], b2);
        ew[2] = cconj(ew[4]); ew[1] = cconj(ew[5]); ew[0] = cconj(ew[6]);
    }
    float2 accA = make_float2(0.f, 0.f), accB = make_float2(0.f, 0.f);
#pragma unroll
    for (int i = 0; i < 7; i++) {
        float2 rowA = make_float2(0.f, 0.f), rowB = make_float2(0.f, 0.f);
#pragma unroll
        for (int j = 0; j < 7; j++) {
            float va = ka[i * 7 + j], vb = kb[i * 7 + j];
            rowA.x += va * ew[j].x; rowA.y += va * ew[j].y;
            rowB.x += vb * ew[j].x; rowB.y += vb * ew[j].y;
        }
        accA = cadd(accA, cmul(eh[i], rowA));
        accB = cadd(accB, cmul(eh[i], rowB));
    }
    size_t idx = (size_t)c * HW + h * 128 + w;
    g_AF[idx] = accA;
    g_BF[idx] = accB;
}

// ---------------- K3: FFT along W + transpose to planar + bf16 split of x ----------------
__global__ void fftw_kernel(const float* __restrict__ x) {
    __shared__ float tile[128][33];
    int bh = blockIdx.y;
    int b = bh >> 7;
    int c0 = blockIdx.x * 32;
    int t = threadIdx.x;
#pragma unroll
    for (int j = 0; j < 16; j++) {
        int i = t + j * 256;
        int w = i >> 5, cl = i & 31;
        float v = x[(size_t)bh * (WD * CC) + (size_t)w * CC + c0 + cl];
        tile[w][cl] = v;
        __nv_bfloat16 hi = __float2bfloat16(v);
        __nv_bfloat16 lo = __float2bfloat16(v - __bfloat162float(hi));
        size_t pi = ((size_t)bh * 128 + w) * 256 + c0 + cl;
        g_XHi[pi] = hi;
        g_XLo[pi] = lo;
    }
    __syncthreads();
    int warp = t >> 5, lane = t & 31;
    int rb = __brev(lane) >> 27;
    int h = bh & 127;
#pragma unroll
    for (int cc4 = 0; cc4 < 4; cc4++) {
        int cl = warp * 4 + cc4;
        float2 v[4];
#pragma unroll
        for (int n1 = 0; n1 < 4; n1++) v[n1] = make_float2(tile[n1 * 32 + lane][cl], 0.f);
        fft128<-1>(v, lane);
        size_t rowoff = (size_t)(b * CC + c0 + cl) * HW + (size_t)h * 128 + rb * 4;
#pragma unroll
        for (int k1 = 0; k1 < 4; k1++) g_XF[rowoff + k1] = v[k1];
    }
}

// ---------------- K2: HMMA GEMM, cp.async 2-stage pipeline + polar-gate epilogue ----------------
// CTA: 128 pixels x 128 effcols; 8 warps (4 m x 2 n), warp tile 32x64.
// K=256 in 4 chunks of 64; stage = {Ah,Al,Bh,Bl}[128][72] bf16 = 72 KB; 2 stages.
#define AS_STRIDE_B 144                       // 72 elems * 2B
#define OFF_AH 0
#define OFF_AL 18432
#define OFF_BH 36864
#define OFF_BL 55296
#define STAGE_BYTES 73728
#define GEMM_SMEM (2 * STAGE_BYTES)           // 147456
#define Z_STRIDE 130

__device__ __forceinline__ void gemm_issue_stage(uint32_t sb, size_t pixbase, int n0,
                                                 int kc, int tid) {
    uint32_t st = sb + (uint32_t)(kc & 1) * STAGE_BYTES;
#pragma unroll
    for (int it = 0; it < 4; it++) {
        int u = tid + it * 256;
        int row = u >> 3, seg = u & 7;
        size_t gofs = (pixbase + row) * 256 + kc * 64 + seg * 8;
        uint32_t d = (uint32_t)(row * AS_STRIDE_B + seg * 16);
        cp16(st + OFF_AH + d, g_XHi + gofs);
        cp16(st + OFF_AL + d, g_XLo + gofs);
    }
#pragma unroll
    for (int it = 0; it < 4; it++) {
        int u = tid + it * 256;
        int row = u >> 3, seg = u & 7;
        size_t gofs = (size_t)(n0 + row) * 256 + kc * 64 + seg * 8;
        uint32_t d = (uint32_t)(row * AS_STRIDE_B + seg * 16);
        cp16(st + OFF_BH + d, g_WbHi + gofs);
        cp16(st + OFF_BL + d, g_WbLo + gofs);
    }
    CP_COMMIT();
}

__global__ __launch_bounds__(256, 1) void gemm_mma_kernel() {
    extern __shared__ char smem[];
    uint32_t sb = smem_u32(smem);
    int tid = threadIdx.x;
    int lane = tid & 31, warp = tid >> 5;
    int wm = warp >> 1, wn = warp & 1;
    int n0 = blockIdx.x * 128;
    int mb = blockIdx.y;
    size_t pixbase = (size_t)mb * 128;

    float acc[2][8][4];
#pragma unroll
    for (int i = 0; i < 2; i++)
#pragma unroll
        for (int j = 0; j < 8; j++)
#pragma unroll
            for (int k = 0; k < 4; k++) acc[i][j][k] = 0.f;

    int sub = lane >> 3, l7 = lane & 7;
    int a_r = ((sub & 1) << 3) + l7;
    int a_k = (sub >> 1) << 3;
    int b_r = ((sub >> 1) << 3) + l7;
    int b_k = (sub & 1) << 3;

    gemm_issue_stage(sb, pixbase, n0, 0, tid);
    gemm_issue_stage(sb, pixbase, n0, 1, tid);

#pragma unroll
    for (int kc = 0; kc < 4; kc++) {
        if (kc < 3) { CP_WAIT1(); } else { CP_WAIT0(); }
        __syncthreads();
        uint32_t st = sb + (uint32_t)(kc & 1) * STAGE_BYTES;
#pragma unroll
        for (int ks = 0; ks < 4; ks++) {
            uint32_t ah[2][4], al[2][4];
#pragma unroll
            for (int mt = 0; mt < 2; mt++) {
                uint32_t aoff = (uint32_t)((wm * 32 + mt * 16 + a_r) * AS_STRIDE_B + (ks * 16 + a_k) * 2);
                ldsm4(ah[mt], st + OFF_AH + aoff);
                ldsm4(al[mt], st + OFF_AL + aoff);
            }
#pragma unroll
            for (int ntp = 0; ntp < 4; ntp++) {
                uint32_t bh[4], bl[4];
                uint32_t boff = (uint32_t)((wn * 64 + ntp * 16 + b_r) * AS_STRIDE_B + (ks * 16 + b_k) * 2);
                ldsm4(bh, st + OFF_BH + boff);
                ldsm4(bl, st + OFF_BL + boff);
#pragma unroll
                for (int mt = 0; mt < 2; mt++) {
                    mma16816(acc[mt][2 * ntp],     ah[mt], bh);
                    mma16816(acc[mt][2 * ntp + 1], ah[mt], bh + 2);
                    mma16816(acc[mt][2 * ntp],     ah[mt], bl);
                    mma16816(acc[mt][2 * ntp + 1], ah[mt], bl + 2);
                    mma16816(acc[mt][2 * ntp],     al[mt], bh);
                    mma16816(acc[mt][2 * ntp + 1], al[mt], bh + 2);
                }
            }
        }
        __syncthreads();
        if (kc + 2 < 4) gemm_issue_stage(sb, pixbase, n0, kc + 2, tid);
    }

    // ---- epilogue: Z (transposed) in SMEM, then gates ----
    float* zs = (float*)smem;
    {
        int r0 = wm * 32 + (lane >> 2);
        int c0 = wn * 64 + 2 * (lane & 3);
#pragma unroll
        for (int mt = 0; mt < 2; mt++)
#pragma unroll
            for (int nt = 0; nt < 8; nt++) {
                int rr = r0 + mt * 16;
                int cc = c0 + nt * 8;
                zs[cc * Z_STRIDE + rr]           = acc[mt][nt][0];
                zs[(cc + 1) * Z_STRIDE + rr]     = acc[mt][nt][1];
                zs[cc * Z_STRIDE + rr + 8]       = acc[mt][nt][2];
                zs[(cc + 1) * Z_STRIDE + rr + 8] = acc[mt][nt][3];
            }
    }
    __syncthreads();
    {
        int pr = tid & 127;
        int half = tid >> 7;
        int pix = mb * 128 + pr;
        int b = pix >> 14;
        int hw = pix & 16383;
#pragma unroll 1
        for (int it = 0; it < 16; it++) {
            int dl = 2 * it + half;
            int e0 = dl * 4;
            float zma = zs[e0 * Z_STRIDE + pr]       + g_bpk[n0 + e0];
            float zpa = zs[(e0 + 1) * Z_STRIDE + pr] + g_bpk[n0 + e0 + 1];
            float zmb = zs[(e0 + 2) * Z_STRIDE + pr] + g_bpk[n0 + e0 + 2];
            float zpb = zs[(e0 + 3) * Z_STRIDE + pr] + g_bpk[n0 + e0 + 3];
            float ma  = 1.0f / (1.0f + __expf(-zma));
            float mbg = 1.0f / (1.0f + __expf(-zmb));
            float sa, ca, sbp, cb;
            __sincosf(zpa, &sa, &ca);
            __sincosf(zpb, &sbp, &cb);
            int d = (n0 >> 2) + dl;
            size_t po = (size_t)(b * 256 + d) * HW + hw;
            g_GA[po] = make_float2(ma * ca, ma * sa);
            g_GB[po] = make_float2(mbg * cb, mbg * sbp);
        }
    }
}

// ---------------- K4: FFT-H + pointwise recurrence + IFFT-H ----------------
__global__ void ffth_pointwise_kernel() {
    __shared__ float2 tile[128][33];
    int plane = blockIdx.y;
    int c = plane & 255;
    int w0 = blockIdx.x * 32;
    int t = threadIdx.x;
    size_t pbase = (size_t)plane * HW;
    size_t cbase = (size_t)c * HW;
#pragma unroll
    for (int j = 0; j < 16; j++) {
        int i = t + j * 256;
        int h = i >> 5, wl = i & 31;
        tile[h][wl] = g_XF[pbase + (size_t)h * 128 + w0 + wl];
    }
    __syncthreads();
    int warp = t >> 5, lane = t & 31;
    int rb = __brev(lane) >> 27;
#pragma unroll
    for (int cc4 = 0; cc4 < 4; cc4++) {
        int wl = warp * 4 + cc4;
        float2 v[4];
#pragma unroll
        for (int n1 = 0; n1 < 4; n1++) v[n1] = tile[n1 * 32 + lane][wl];
        fft128<-1>(v, lane);
#pragma unroll
        for (int k1 = 0; k1 < 4; k1++) tile[rb * 4 + k1][wl] = v[k1];
    }
    __syncthreads();
#pragma unroll
    for (int j = 0; j < 16; j++) {
        int i = t + j * 256;
        int h = i >> 5, wl = i & 31;
        size_t off = (size_t)h * 128 + w0 + wl;
        float2 xf = tile[h][wl];
        float2 ga = g_GA[pbase + off];
        float2 gb = g_GB[pbase + off];
        float2 af = g_AF[cbase + off];
        float2 bf = g_BF[cbase + off];
        float2 a  = cmul(ga, af);
        float2 bb = cmul(cmul(gb, bf), xf);
        float2 a2 = cmul(a, a);
        float2 a4 = cmul(a2, a2);
        float2 p1 = make_float2(1.f + a.x,  a.y);
        float2 p2 = make_float2(1.f + a2.x, a2.y);
        float2 p4 = make_float2(1.f + a4.x, a4.y);
        float2 hf = cmul(bb, cmul(cmul(p1, p2), p4));
        tile[h][wl] = hf;
    }
    __syncthreads();
#pragma unroll
    for (int cc4 = 0; cc4 < 4; cc4++) {
        int wl = warp * 4 + cc4;
        float2 v[4];
#pragma unroll
        for (int n1 = 0; n1 < 4; n1++) v[n1] = tile[n1 * 32 + lane][wl];
        fft128<+1>(v, lane);
#pragma unroll
        for (int k1 = 0; k1 < 4; k1++) tile[rb * 4 + k1][wl] = v[k1];
    }
    __syncthreads();
#pragma unroll
    for (int j = 0; j < 16; j++) {
        int i = t + j * 256;
        int h = i >> 5, wl = i & 31;
        g_XF[pbase + (size_t)h * 128 + w0 + wl] = tile[h][wl];
    }
}

// ---------------- K5: IFFT along W + transpose to (B,H,W,C) real out ----------------
__global__ void ifftw_out_kernel(float* __restrict__ out) {
    __shared__ float tile[128][33];
    int bh = blockIdx.y;
    int b = bh >> 7;
    int h = bh & 127;
    int c0 = blockIdx.x * 32;
    int t = threadIdx.x;
    int warp = t >> 5, lane = t & 31;
    int rb = __brev(lane) >> 27;
    const float inv = 1.0f / 16384.0f;
#pragma unroll
    for (int cc4 = 0; cc4 < 4; cc4++) {
        int cl = warp * 4 + cc4;
        size_t rowoff = (size_t)(b * CC + c0 + cl) * HW + (size_t)h * 128;
        float2 v[4];
#pragma unroll
        for (int n1 = 0; n1 < 4; n1++) v[n1] = g_XF[rowoff + n1 * 32 + lane];
        fft128<+1>(v, lane);
#pragma unroll
        for (int k1 = 0; k1 < 4; k1++) tile[rb * 4 + k1][cl] = v[k1].x * inv;
    }
    __syncthreads();
#pragma unroll
    for (int j = 0; j < 16; j++) {
        int i = t + j * 256;
        int w = i >> 5, cl = i & 31;
        out[(size_t)bh * (WD * CC) + (size_t)w * CC + c0 + cl] = tile[w][cl];
    }
}

extern "C" void kernel_launch(void* const* d_in, const int* in_sizes, int n_in,
                              void* d_out, int out_size) {
    const float* x   = (const float*)d_in[0];
    const float* Ak  = (const float*)d_in[1];
    const float* Bk  = (const float*)d_in[2];
    const float* Wma = (const float*)d_in[3];
    const float* bma = (const float*)d_in[4];
    const float* Wpa = (const float*)d_in[5];
    const float* bpa = (const float*)d_in[6];
    const float* Wmb = (const float*)d_in[7];
    const float* bmb = (const float*)d_in[8];
    const float* Wpb = (const float*)d_in[9];
    const float* bpb = (const float*)d_in[10];
    float* out = (float*)d_out;

    cudaFuncSetAttribute(gemm_mma_kernel, cudaFuncAttributeMaxDynamicSharedMemorySize, GEMM_SMEM);

    pack_kernel<<<1024, 256>>>(Wma, Wpa, Wmb, Wpb, bma, bpa, bmb, bpb);
    kfreq_kernel<<<dim3(128, 256), 128>>>(Ak, Bk);
    fftw_kernel<<<dim3(8, 1024), 256>>>(x);
    gemm_mma_kernel<<<dim3(8, 1024), 256, GEMM_SMEM>>>();
    ffth_pointwise_kernel<<<dim3(4, 2048), 256>>>();
    ifftw_out_kernel<<<dim3(8, 1024), 256>>>(out);
}